// round 1
// baseline (speedup 1.0000x reference)
#include <cuda_runtime.h>
#include <math.h>

#define NB 8
#define NT 2048
#define NC 512   // IN_CH = KEY = VAL

// Scratch (allocation-free rule: __device__ globals)
__device__ float g_q[NB * NT * NC];
__device__ float g_k[NB * NT * NC];
__device__ float g_v[NB * NT * NC];
__device__ float g_lg[(size_t)NB * NT * NT];   // logits stored TRANSPOSED: [b][s][t]

// ---------------------------------------------------------------------------
// Generic 128x128x8 fp32 tiled GEMM, 256 threads, 8x8 per-thread microtile.
// ALayout: 0 -> A element (m,k) = A[m*lda + k]   (row-major MK)
//          1 -> A element (m,k) = A[k*lda + m]   (k-major, m contiguous)
// BLayout: 0 -> B element (k,n) = B[k*ldb + n]   (k-major, n contiguous)
//          1 -> B element (k,n) = B[n*ldb + k]   (n-major, k contiguous)
// CSKIP: skip blocks fully below causal diagonal (for logits: m=s, n=t, need t>=s)
// CKLIM: clamp k-loop to k < m0+BM (for read GEMM: k=s, m=t, P[s,t]=0 for s>t)
// All dims assumed multiples of tile sizes (true for this problem).
// ---------------------------------------------------------------------------
#define BM 128
#define BN 128
#define BKK 8
#define TM 8
#define TN 8

template<int AL, int BL, bool BIAS, bool CSKIP, bool CKLIM>
__global__ __launch_bounds__(256, 2)
void gemm_k(const float* __restrict__ Ag, const float* __restrict__ Bg,
            const float* __restrict__ bias, float* __restrict__ Cg,
            int M, int N, int Ktot, int lda, int ldb, int ldc,
            size_t sA, size_t sB, size_t sC)
{
    const int m0 = blockIdx.y * BM;
    const int n0 = blockIdx.x * BN;
    if (CSKIP && (n0 + BN - 1) < m0) return;  // fully-masked causal tile

    const float* A = Ag + (size_t)blockIdx.z * sA;
    const float* Bp = Bg + (size_t)blockIdx.z * sB;
    float* C = Cg + (size_t)blockIdx.z * sC;

    __shared__ float As[BKK][BM];
    __shared__ float Bs[BKK][BN];

    const int tid = threadIdx.x;
    const int tx = tid & 15;   // n microtile
    const int ty = tid >> 4;   // m microtile

    float acc[TM][TN];
#pragma unroll
    for (int i = 0; i < TM; i++)
#pragma unroll
        for (int j = 0; j < TN; j++) acc[i][j] = 0.f;

    const int kend = CKLIM ? min(Ktot, m0 + BM) : Ktot;

    for (int k0 = 0; k0 < kend; k0 += BKK) {
        // ---- load A tile into As[k][m] ----
        if (AL == 0) {
            const int row = tid >> 1;          // 0..127 (m)
            const int kc = (tid & 1) * 4;      // 0 or 4 (k)
            float4 va = *(const float4*)(A + (size_t)(m0 + row) * lda + k0 + kc);
            As[kc + 0][row] = va.x;
            As[kc + 1][row] = va.y;
            As[kc + 2][row] = va.z;
            As[kc + 3][row] = va.w;
        } else {
            const int kr = tid >> 5;           // 0..7 (k)
            const int mc = (tid & 31) * 4;     // m, contiguous
            float4 va = *(const float4*)(A + (size_t)(k0 + kr) * lda + m0 + mc);
            *(float4*)&As[kr][mc] = va;
        }
        // ---- load B tile into Bs[k][n] ----
        if (BL == 0) {
            const int kr = tid >> 5;
            const int nc = (tid & 31) * 4;
            float4 vb = *(const float4*)(Bp + (size_t)(k0 + kr) * ldb + n0 + nc);
            *(float4*)&Bs[kr][nc] = vb;
        } else {
            const int row = tid >> 1;          // n
            const int kc = (tid & 1) * 4;
            float4 vb = *(const float4*)(Bp + (size_t)(n0 + row) * ldb + k0 + kc);
            Bs[kc + 0][row] = vb.x;
            Bs[kc + 1][row] = vb.y;
            Bs[kc + 2][row] = vb.z;
            Bs[kc + 3][row] = vb.w;
        }
        __syncthreads();

#pragma unroll
        for (int kk = 0; kk < BKK; kk++) {
            float a[TM], b[TN];
            *(float4*)&a[0] = *(float4*)&As[kk][ty * TM];
            *(float4*)&a[4] = *(float4*)&As[kk][ty * TM + 4];
            *(float4*)&b[0] = *(float4*)&Bs[kk][tx * TN];
            *(float4*)&b[4] = *(float4*)&Bs[kk][tx * TN + 4];
#pragma unroll
            for (int i = 0; i < TM; i++)
#pragma unroll
                for (int j = 0; j < TN; j++)
                    acc[i][j] += a[i] * b[j];
        }
        __syncthreads();
    }

    // ---- epilogue ----
#pragma unroll
    for (int i = 0; i < TM; i++) {
        const int m = m0 + ty * TM + i;
#pragma unroll
        for (int j = 0; j < TN; j += 4) {
            const int n = n0 + tx * TN + j;
            float4 r = make_float4(acc[i][j], acc[i][j + 1], acc[i][j + 2], acc[i][j + 3]);
            if (BIAS) {
                r.x += bias[n + 0];
                r.y += bias[n + 1];
                r.z += bias[n + 2];
                r.w += bias[n + 3];
            }
            *(float4*)(C + (size_t)m * ldc + n) = r;
        }
    }
}

// ---------------------------------------------------------------------------
// Column softmax (reference softmaxes over QUERY axis t, per key column s).
// Logits stored transposed lgT[b][s][t] -> contiguous softmax over t.
// Valid entries: t >= s (causal). Masked entries become exactly 0.
// ---------------------------------------------------------------------------
__global__ void softmax_col_k(float* __restrict__ lg)
{
    const int s = blockIdx.x;
    const int b = blockIdx.y;
    float* row = lg + ((size_t)b * NT + s) * (size_t)NT;

    __shared__ float buf[NT];
    __shared__ float red[256];
    const int tid = threadIdx.x;
    const float scale = 0.044194173824159216f;  // 1/sqrt(512)
    const float NEG_INF = -__int_as_float(0x7f800000);

    float lmax = NEG_INF;
    for (int t = tid; t < NT; t += 256) {
        float xv = (t >= s) ? row[t] * scale : NEG_INF;
        buf[t] = xv;
        lmax = fmaxf(lmax, xv);
    }
    red[tid] = lmax;
    __syncthreads();
    for (int off = 128; off > 0; off >>= 1) {
        if (tid < off) red[tid] = fmaxf(red[tid], red[tid + off]);
        __syncthreads();
    }
    const float mx = red[0];
    __syncthreads();

    float lsum = 0.f;
    for (int t = tid; t < NT; t += 256) {
        float e = (t >= s) ? expf(buf[t] - mx) : 0.f;
        buf[t] = e;
        lsum += e;
    }
    red[tid] = lsum;
    __syncthreads();
    for (int off = 128; off > 0; off >>= 1) {
        if (tid < off) red[tid] += red[tid + off];
        __syncthreads();
    }
    const float inv = 1.f / red[0];
    __syncthreads();

    for (int t = tid; t < NT; t += 256) row[t] = buf[t] * inv;
}

// Copy x into out[..., 0:512] (out row = 1024 floats = 256 float4, first 128 are x)
__global__ void copy_x_k(const float4* __restrict__ x4, float4* __restrict__ out4)
{
    const size_t i = (size_t)blockIdx.x * blockDim.x + threadIdx.x;
    // total float4s = NB*NT*NC/4 = 2,097,152
    const size_t row = i >> 7;     // / 128
    const size_t col = i & 127;
    out4[row * 256 + col] = x4[i];
}

extern "C" void kernel_launch(void* const* d_in, const int* in_sizes, int n_in,
                              void* d_out, int out_size)
{
    const float* x  = (const float*)d_in[0];
    const float* Wq = (const float*)d_in[1];
    const float* bq = (const float*)d_in[2];
    const float* Wk = (const float*)d_in[3];
    const float* bk = (const float*)d_in[4];
    const float* Wv = (const float*)d_in[5];
    const float* bv = (const float*)d_in[6];
    float* out = (float*)d_out;

    float *q, *k, *v, *lg;
    cudaGetSymbolAddress((void**)&q, g_q);
    cudaGetSymbolAddress((void**)&k, g_k);
    cudaGetSymbolAddress((void**)&v, g_v);
    cudaGetSymbolAddress((void**)&lg, g_lg);

    const size_t strBT = (size_t)NT * NC;        // per-batch q/k/v stride
    const size_t strLG = (size_t)NT * NT;        // per-batch logits stride
    const size_t strOUT = (size_t)NT * (2 * NC); // per-batch out stride

    // 1) QKV projections: [16384,512] @ [512,512] + bias
    {
        dim3 grid(NC / BN, (NB * NT) / BM, 1);   // (4, 128)
        gemm_k<0, 0, true, false, false><<<grid, 256>>>(
            x, Wq, bq, q, NB * NT, NC, NC, NC, NC, NC, 0, 0, 0);
        gemm_k<0, 0, true, false, false><<<grid, 256>>>(
            x, Wk, bk, k, NB * NT, NC, NC, NC, NC, NC, 0, 0, 0);
        gemm_k<0, 0, true, false, false><<<grid, 256>>>(
            x, Wv, bv, v, NB * NT, NC, NC, NC, NC, NC, 0, 0, 0);
    }

    // 2) logitsT[b][s][t] = sum_c k[b,s,c] * q[b,t,c]   (NT layout; causal skip)
    {
        dim3 grid(NT / BN, NT / BM, NB);         // (16, 16, 8)
        gemm_k<0, 1, false, true, false><<<grid, 256>>>(
            k, q, nullptr, lg, NT, NT, NC, NC, NC, NT, strBT, strBT, strLG);
    }

    // 3) column softmax over t (contiguous), in place -> probsT
    softmax_col_k<<<dim3(NT, NB), 256>>>(lg);

    // 4) read[b][t][v] = sum_s probsT[b][s][t] * v[b][s][v]  -> out[..., 512:1024]
    {
        dim3 grid(NC / BN, NT / BM, NB);         // (4, 16, 8)
        gemm_k<1, 0, false, false, true><<<grid, 256>>>(
            lg, v, nullptr, out + NC, NT, NC, NT, NT, NC, 2 * NC,
            strLG, strBT, strOUT);
    }

    // 5) out[..., 0:512] = x
    copy_x_k<<<(NB * NT * NC / 4) / 256, 256>>>((const float4*)x, (float4*)out);
}

// round 3
// speedup vs baseline: 4.0361x; 4.0361x over previous
#include <cuda_runtime.h>
#include <cstdint>
#include <math.h>

#define NB 8
#define NT 2048
#define NC 512
#define SCALE 0.04419417382415922f   // 1/sqrt(512)

// ---------------- scratch (__device__ globals; allocation-free rule) --------
__device__ __align__(256) float g_q [NB * NT * NC];
__device__ __align__(256) float g_k [NB * NT * NC];
__device__ __align__(256) float g_v [NB * NT * NC];          // [b][t][c]
__device__ __align__(256) float g_vT[NB * NT * NC];          // [b][c][t]
__device__ __align__(256) float g_wT[3 * NC * NC];           // WqT,WkT,WvT
__device__ __align__(256) float g_lg[(size_t)NB * NT * NT];  // lgT [b][s][t]
__device__ __align__(256) float g_p [(size_t)NB * NT * NT];  // P'  [b][t][s]
__device__ float g_mx [NB * NT];
__device__ float g_inv[NB * NT];

// ---------------- helpers ---------------------------------------------------
__device__ __forceinline__ uint32_t cvt2bf(float hi_, float lo_) {
    // d.hi16 = bf16(hi_), d.lo16 = bf16(lo_)  -> halfword memory order [lo_, hi_]
    uint32_t r;
    asm("cvt.rn.satfinite.bf16x2.f32 %0, %1, %2;" : "=r"(r) : "f"(hi_), "f"(lo_));
    return r;
}

__device__ __forceinline__ void mma_bf16(float* c, const uint32_t* a, const uint32_t* b) {
    asm volatile(
        "mma.sync.aligned.m16n8k16.row.col.f32.bf16.bf16.f32 "
        "{%0,%1,%2,%3}, {%4,%5,%6,%7}, {%8,%9}, {%0,%1,%2,%3};"
        : "+f"(c[0]), "+f"(c[1]), "+f"(c[2]), "+f"(c[3])
        : "r"(a[0]), "r"(a[1]), "r"(a[2]), "r"(a[3]), "r"(b[0]), "r"(b[1]));
}

// convert a float4 (4 consecutive k values) to hi/lo bf16x2 pairs and store
// into H tile (at base+off) and L tile (at base+8192+off)
__device__ __forceinline__ void cvt_store(char* base, uint32_t off, float4 v) {
    const uint32_t h01 = cvt2bf(v.y, v.x);
    const uint32_t h23 = cvt2bf(v.w, v.z);
    const float hx = __uint_as_float(h01 << 16);
    const float hy = __uint_as_float(h01 & 0xffff0000u);
    const float hz = __uint_as_float(h23 << 16);
    const float hw = __uint_as_float(h23 & 0xffff0000u);
    const uint32_t l01 = cvt2bf(v.y - hy, v.x - hx);
    const uint32_t l23 = cvt2bf(v.w - hw, v.z - hz);
    *(uint2*)(base + off)        = make_uint2(h01, h23);
    *(uint2*)(base + 8192 + off) = make_uint2(l01, l23);
}

// ---------------------------------------------------------------------------
// bf16 split-precision GEMM via mma.sync (HMMA):
//   D[m][n] = sum_k A[m][k] * B[n][k]   (A,B fp32, both k-contiguous)
// CTA tile 128x128, BK=32, 256 threads, warp tile 64x32.
// smem per stage: Ah|Al|Bh|Bl, 8KB each (128 rows x 64B), XOR-swizzled words.
// CSKIP: skip tile if n0+127 < m0 (causal logits).  CKLIM: kend = m0+128.
// ---------------------------------------------------------------------------
template<bool BIAS, bool CSKIP, bool CKLIM>
__global__ __launch_bounds__(256, 1)
void gemm_mma(const float* __restrict__ Ag, const float* __restrict__ Bg,
              const float* __restrict__ bias, float* __restrict__ Cg,
              int lda, int ldb, int ldc, int Ktot,
              size_t sA, size_t sB, size_t sC)
{
    extern __shared__ char smem[];
    const int m0 = blockIdx.y * 128;
    const int n0 = blockIdx.x * 128;
    if (CSKIP && (n0 + 127) < m0) return;

    const float* A = Ag + (size_t)blockIdx.z * sA;
    const float* B = Bg + (size_t)blockIdx.z * sB;

    const int tid = threadIdx.x;
    const int lane = tid & 31;
    const int wid = tid >> 5;
    const int warp_m = (wid & 1) * 64;
    const int warp_n = (wid >> 1) * 32;
    const int g  = lane >> 2;    // group id (row within 8)
    const int tg = lane & 3;     // thread-in-group

    // fragment smem column offsets (swizzle folded in); rows are == g (mod 8)
    uint32_t colOff[4];
    {
        const uint32_t w0 = tg >> 1, sub4 = (tg & 1) * 4;
#pragma unroll
        for (int j = 0; j < 4; j++)
            colOff[j] = (((w0 + 2 * j) ^ (uint32_t)g) << 3) + sub4;
    }
    uint32_t aoff0[4], aoff1[4], boff[4];
#pragma unroll
    for (int mt = 0; mt < 4; mt++) {
        aoff0[mt] = (uint32_t)(warp_m + mt * 16 + g) * 64;
        aoff1[mt] = aoff0[mt] + 8 * 64;
    }
#pragma unroll
    for (int nt = 0; nt < 4; nt++)
        boff[nt] = (uint32_t)(warp_n + nt * 8 + g) * 64;

    // loader indices: 4 float4 per thread per operand tile
    const int lrow = tid >> 3;           // 0..31 (+32*i)
    const int lkg  = tid & 7;            // float4 index within row

    float acc[4][4][4];
#pragma unroll
    for (int mt = 0; mt < 4; mt++)
#pragma unroll
        for (int nt = 0; nt < 4; nt++)
#pragma unroll
            for (int r = 0; r < 4; r++) acc[mt][nt][r] = 0.f;

    const int kend = CKLIM ? min(Ktot, m0 + 128) : Ktot;
    const int nch = kend >> 5;

    float4 pa[4], pb[4];
    // preload chunk 0
#pragma unroll
    for (int i = 0; i < 4; i++) {
        const int row = lrow + i * 32;
        pa[i] = *(const float4*)(A + (size_t)(m0 + row) * lda + lkg * 4);
        pb[i] = *(const float4*)(B + (size_t)(n0 + row) * ldb + lkg * 4);
    }
    {
        char* base = smem;   // stage 0
#pragma unroll
        for (int i = 0; i < 4; i++) {
            const int row = lrow + i * 32;
            const uint32_t off = (uint32_t)row * 64 + ((uint32_t)(lkg ^ (row & 7)) << 3);
            cvt_store(base,         off, pa[i]);
            cvt_store(base + 16384, off, pb[i]);
        }
    }
    __syncthreads();

    for (int c = 0; c < nch; c++) {
        if (c + 1 < nch) {
            const int k0 = (c + 1) << 5;
#pragma unroll
            for (int i = 0; i < 4; i++) {
                const int row = lrow + i * 32;
                pa[i] = *(const float4*)(A + (size_t)(m0 + row) * lda + k0 + lkg * 4);
                pb[i] = *(const float4*)(B + (size_t)(n0 + row) * ldb + k0 + lkg * 4);
            }
        }

        // ---- compute from stage c&1 ----
        {
            const char* base = smem + (size_t)(c & 1) * 32768;
#pragma unroll
            for (int ks = 0; ks < 2; ks++) {
                const uint32_t co0 = colOff[2 * ks];
                const uint32_t co1 = colOff[2 * ks + 1];
                uint32_t ah[4][4], al[4][4], bh[4][2], bl[4][2];
#pragma unroll
                for (int mt = 0; mt < 4; mt++) {
                    ah[mt][0] = *(const uint32_t*)(base + aoff0[mt] + co0);
                    ah[mt][1] = *(const uint32_t*)(base + aoff1[mt] + co0);
                    ah[mt][2] = *(const uint32_t*)(base + aoff0[mt] + co1);
                    ah[mt][3] = *(const uint32_t*)(base + aoff1[mt] + co1);
                    al[mt][0] = *(const uint32_t*)(base + 8192 + aoff0[mt] + co0);
                    al[mt][1] = *(const uint32_t*)(base + 8192 + aoff1[mt] + co0);
                    al[mt][2] = *(const uint32_t*)(base + 8192 + aoff0[mt] + co1);
                    al[mt][3] = *(const uint32_t*)(base + 8192 + aoff1[mt] + co1);
                }
#pragma unroll
                for (int nt = 0; nt < 4; nt++) {
                    bh[nt][0] = *(const uint32_t*)(base + 16384 + boff[nt] + co0);
                    bh[nt][1] = *(const uint32_t*)(base + 16384 + boff[nt] + co1);
                    bl[nt][0] = *(const uint32_t*)(base + 24576 + boff[nt] + co0);
                    bl[nt][1] = *(const uint32_t*)(base + 24576 + boff[nt] + co1);
                }
#pragma unroll
                for (int mt = 0; mt < 4; mt++)
#pragma unroll
                    for (int nt = 0; nt < 4; nt++) {
                        mma_bf16(acc[mt][nt], ah[mt], bh[nt]);
                        mma_bf16(acc[mt][nt], ah[mt], bl[nt]);
                        mma_bf16(acc[mt][nt], al[mt], bh[nt]);
                    }
            }
        }

        // ---- store next chunk into other stage ----
        if (c + 1 < nch) {
            char* base = smem + (size_t)((c + 1) & 1) * 32768;
#pragma unroll
            for (int i = 0; i < 4; i++) {
                const int row = lrow + i * 32;
                const uint32_t off = (uint32_t)row * 64 + ((uint32_t)(lkg ^ (row & 7)) << 3);
                cvt_store(base,         off, pa[i]);
                cvt_store(base + 16384, off, pb[i]);
            }
        }
        __syncthreads();
    }

    // ---- epilogue ----
    float* C = Cg + (size_t)blockIdx.z * sC;
#pragma unroll
    for (int mt = 0; mt < 4; mt++) {
        const int m = m0 + warp_m + mt * 16 + g;
#pragma unroll
        for (int nt = 0; nt < 4; nt++) {
            const int n = n0 + warp_n + nt * 8 + tg * 2;
            float2 v0 = make_float2(acc[mt][nt][0], acc[mt][nt][1]);
            float2 v1 = make_float2(acc[mt][nt][2], acc[mt][nt][3]);
            if (BIAS) {
                const float b0 = bias[n], b1 = bias[n + 1];
                v0.x += b0; v0.y += b1;
                v1.x += b0; v1.y += b1;
            }
            *(float2*)(C + (size_t)m * ldc + n)       = v0;
            *(float2*)(C + (size_t)(m + 8) * ldc + n) = v1;
        }
    }
}

// ---------------------------------------------------------------------------
// softmax pass 1: per key-column s, reduce over t >= s -> mx[s], 1/sum
// ---------------------------------------------------------------------------
__global__ void softmax_p1(const float* __restrict__ lg,
                           float* __restrict__ mx, float* __restrict__ inv)
{
    const int s = blockIdx.x, b = blockIdx.y;
    const float* row = lg + ((size_t)b * NT + s) * NT;
    __shared__ float red[256];
    const int tid = threadIdx.x;

    float lmax = -3.4e38f;
    for (int t = s + tid; t < NT; t += 256) lmax = fmaxf(lmax, row[t]);
    red[tid] = lmax;
    __syncthreads();
    for (int off = 128; off > 0; off >>= 1) {
        if (tid < off) red[tid] = fmaxf(red[tid], red[tid + off]);
        __syncthreads();
    }
    const float m = red[0] * SCALE;
    __syncthreads();

    float lsum = 0.f;
    for (int t = s + tid; t < NT; t += 256) lsum += __expf(row[t] * SCALE - m);
    red[tid] = lsum;
    __syncthreads();
    for (int off = 128; off > 0; off >>= 1) {
        if (tid < off) red[tid] += red[tid + off];
        __syncthreads();
    }
    if (tid == 0) {
        mx[b * NT + s]  = m;
        inv[b * NT + s] = 1.f / red[0];
    }
}

// ---------------------------------------------------------------------------
// softmax pass 2: exp + normalize + transpose -> P'[b][t][s] (zeros for t<s)
// ---------------------------------------------------------------------------
__global__ void softmax_p2(const float* __restrict__ lg, const float* __restrict__ mx,
                           const float* __restrict__ inv, float* __restrict__ P)
{
    const int ti = blockIdx.x, si = blockIdx.y, b = blockIdx.z;
    if (si * 32 >= ti * 32 + 128) return;   // never read by the read-GEMM
    __shared__ float tile[32][33];
    const int tx = threadIdx.x & 31, ty = threadIdx.x >> 5;
    const int t = ti * 32 + tx;
#pragma unroll
    for (int r = 0; r < 4; r++) {
        const int s = si * 32 + ty + r * 8;
        float p = 0.f;
        if (t >= s) {
            const float val = lg[((size_t)b * NT + s) * NT + t];
            p = __expf(val * SCALE - mx[b * NT + s]) * inv[b * NT + s];
        }
        tile[ty + r * 8][tx] = p;
    }
    __syncthreads();
    const int s2 = si * 32 + tx;
#pragma unroll
    for (int r = 0; r < 4; r++) {
        const int t2 = ti * 32 + ty + r * 8;
        P[((size_t)b * NT + t2) * NT + s2] = tile[tx][ty + r * 8];
    }
}

// 512x512 transpose: WT[n][k] = W[k][n]
__global__ void trans512(const float* __restrict__ W, float* __restrict__ WT)
{
    __shared__ float tile[32][33];
    const int tx = threadIdx.x & 31, ty = threadIdx.x >> 5;
    const int c0 = blockIdx.x * 32, r0 = blockIdx.y * 32;
#pragma unroll
    for (int r = 0; r < 4; r++)
        tile[ty + r * 8][tx] = W[(size_t)(r0 + ty + r * 8) * NC + c0 + tx];
    __syncthreads();
#pragma unroll
    for (int r = 0; r < 4; r++)
        WT[(size_t)(c0 + ty + r * 8) * NC + r0 + tx] = tile[tx][ty + r * 8];
}

// v[b][t][c] -> vT[b][c][t]
__global__ void trans_btc(const float* __restrict__ in, float* __restrict__ out)
{
    __shared__ float tile[32][33];
    const int c0 = blockIdx.x * 32, t0 = blockIdx.y * 32, b = blockIdx.z;
    const float* ip = in + (size_t)b * NT * NC;
    float* op = out + (size_t)b * NT * NC;
    const int tx = threadIdx.x & 31, ty = threadIdx.x >> 5;
#pragma unroll
    for (int r = 0; r < 4; r++)
        tile[ty + r * 8][tx] = ip[(size_t)(t0 + ty + r * 8) * NC + c0 + tx];
    __syncthreads();
#pragma unroll
    for (int r = 0; r < 4; r++)
        op[(size_t)(c0 + ty + r * 8) * NT + t0 + tx] = tile[tx][ty + r * 8];
}

// out[..., 0:512] = x
__global__ void copy_x_k(const float4* __restrict__ x4, float4* __restrict__ out4)
{
    const size_t i = (size_t)blockIdx.x * blockDim.x + threadIdx.x;
    const size_t row = i >> 7;
    const size_t col = i & 127;
    out4[row * 256 + col] = x4[i];
}

// ---------------------------------------------------------------------------
extern "C" void kernel_launch(void* const* d_in, const int* in_sizes, int n_in,
                              void* d_out, int out_size)
{
    const float* x  = (const float*)d_in[0];
    const float* Wq = (const float*)d_in[1];
    const float* bq = (const float*)d_in[2];
    const float* Wk = (const float*)d_in[3];
    const float* bk = (const float*)d_in[4];
    const float* Wv = (const float*)d_in[5];
    const float* bv = (const float*)d_in[6];
    float* out = (float*)d_out;

    float *q, *k, *v, *vT, *wT, *lg, *p, *mx, *inv;
    cudaGetSymbolAddress((void**)&q,  g_q);
    cudaGetSymbolAddress((void**)&k,  g_k);
    cudaGetSymbolAddress((void**)&v,  g_v);
    cudaGetSymbolAddress((void**)&vT, g_vT);
    cudaGetSymbolAddress((void**)&wT, g_wT);
    cudaGetSymbolAddress((void**)&lg, g_lg);
    cudaGetSymbolAddress((void**)&p,  g_p);
    cudaGetSymbolAddress((void**)&mx, g_mx);
    cudaGetSymbolAddress((void**)&inv, g_inv);

    const int SMEM = 65536;
    cudaFuncSetAttribute(gemm_mma<true,  false, false>, cudaFuncAttributeMaxDynamicSharedMemorySize, SMEM);
    cudaFuncSetAttribute(gemm_mma<false, true,  false>, cudaFuncAttributeMaxDynamicSharedMemorySize, SMEM);
    cudaFuncSetAttribute(gemm_mma<false, false, true >, cudaFuncAttributeMaxDynamicSharedMemorySize, SMEM);

    const size_t strBT  = (size_t)NT * NC;
    const size_t strLG  = (size_t)NT * NT;
    const size_t strOUT = (size_t)NT * (2 * NC);

    // 0) transpose weights -> [N][K]
    trans512<<<dim3(16, 16), 256>>>(Wq, wT + 0 * NC * NC);
    trans512<<<dim3(16, 16), 256>>>(Wk, wT + 1 * NC * NC);
    trans512<<<dim3(16, 16), 256>>>(Wv, wT + 2 * NC * NC);

    // 1) QKV projections (M=16384, N=512, K=512)
    {
        dim3 grid(NC / 128, (NB * NT) / 128, 1);
        gemm_mma<true, false, false><<<grid, 256, SMEM>>>(
            x, wT + 0 * NC * NC, bq, q, NC, NC, NC, NC, 0, 0, 0);
        gemm_mma<true, false, false><<<grid, 256, SMEM>>>(
            x, wT + 1 * NC * NC, bk, k, NC, NC, NC, NC, 0, 0, 0);
        gemm_mma<true, false, false><<<grid, 256, SMEM>>>(
            x, wT + 2 * NC * NC, bv, v, NC, NC, NC, NC, 0, 0, 0);
    }

    // 1b) v -> vT  [b][c][t]
    trans_btc<<<dim3(NC / 32, NT / 32, NB), 256>>>(v, vT);

    // 2) logitsT[b][s][t] = sum_c k[b,s,c] * q[b,t,c]  (causal tile skip)
    {
        dim3 grid(NT / 128, NT / 128, NB);
        gemm_mma<false, true, false><<<grid, 256, SMEM>>>(
            k, q, nullptr, lg, NC, NC, NT, NC, strBT, strBT, strLG);
    }

    // 3) softmax over t (column softmax) -> P'[b][t][s]
    softmax_p1<<<dim3(NT, NB), 256>>>(lg, mx, inv);
    softmax_p2<<<dim3(NT / 32, NT / 32, NB), 256>>>(lg, mx, inv, p);

    // 4) read[b][t][v] = sum_s P'[b,t,s] * vT[b,v,s]  -> out[..., 512:1024]
    {
        dim3 grid(NC / 128, NT / 128, NB);
        gemm_mma<false, false, true><<<grid, 256, SMEM>>>(
            p, vT, nullptr, out + NC, NT, NT, 2 * NC, NT,
            strLG, (size_t)NC * NT, strOUT);
    }

    // 5) out[..., 0:512] = x
    copy_x_k<<<(NB * NT * NC / 4) / 256, 256>>>((const float4*)x, (float4*)out);
}